// round 1
// baseline (speedup 1.0000x reference)
#include <cuda_runtime.h>
#include <cuda_bf16.h>
#include <cstddef>

// Problem constants
#define BB   2
#define TT   2048
#define DD   1024
#define HH   16
#define HDD  64
#define FFD  4096
#define MT   (BB*TT)          // 4096 rows total

// ---------------------------------------------------------------------------
// Scratch (static device globals; no allocation at runtime)
// ---------------------------------------------------------------------------
__device__ float g_h  [MT*DD];        // pre-norm output (kept for residual)
__device__ float g_q  [MT*DD];
__device__ float g_k  [MT*DD];
__device__ float g_v  [MT*DD];
__device__ float g_S  [(size_t)BB*HH*TT*TT]; // 512 MB scores/probs
__device__ float g_ao [MT*DD];        // attention output (pre o-proj)
__device__ float g_tmp[MT*DD];        // o-proj out, later FFN down out
__device__ float g_y  [MT*DD];        // post-attn normed
__device__ float g_mid[MT*FFD];       // FFN hidden

// ---------------------------------------------------------------------------
// RMSNorm: out[row] = (a[row] (+ b[row])) * rsqrt(mean(sq)+eps) * w
// grid = rows (4096), block = 256, D = 1024 (4 elems/thread)
// ---------------------------------------------------------------------------
__global__ void __launch_bounds__(256) rmsnorm_kernel(
    const float* __restrict__ a, const float* __restrict__ b,
    const float* __restrict__ w, float* __restrict__ out)
{
    int row = blockIdx.x;
    size_t base = (size_t)row * DD;
    float v[4];
    float ss = 0.f;
#pragma unroll
    for (int t = 0; t < 4; t++) {
        int c = threadIdx.x + t * 256;
        float x = a[base + c];
        if (b) x += b[base + c];
        v[t] = x;
        ss += x * x;
    }
    __shared__ float red[8];
#pragma unroll
    for (int o = 16; o; o >>= 1) ss += __shfl_xor_sync(0xffffffffu, ss, o);
    if ((threadIdx.x & 31) == 0) red[threadIdx.x >> 5] = ss;
    __syncthreads();
    if (threadIdx.x == 0) {
        float tot = 0.f;
#pragma unroll
        for (int i = 0; i < 8; i++) tot += red[i];
        red[0] = tot;
    }
    __syncthreads();
    float scale = rsqrtf(red[0] * (1.0f / DD) + 1e-6f);
#pragma unroll
    for (int t = 0; t < 4; t++) {
        int c = threadIdx.x + t * 256;
        out[base + c] = v[t] * scale * w[c];
    }
}

// ---------------------------------------------------------------------------
// SIMT fp32 GEMM: C[M,N] = op(A[M,K] @ B[K,N]); row-major; M,N %128==0, K%8==0
// BM=BN=128, BK=8, 256 threads, 8x8 per thread. EPI: 0=none, 1=SiLU
// ---------------------------------------------------------------------------
template <int EPI>
__global__ void __launch_bounds__(256) sgemm_kernel(
    const float* __restrict__ A, const float* __restrict__ B,
    float* __restrict__ C, int M, int N, int K)
{
    __shared__ float As[8][128];
    __shared__ float Bs[8][128];
    int tid = threadIdx.x;
    int bx = blockIdx.x, by = blockIdx.y;

    int arow = tid >> 1;          // 0..127
    int acol = (tid & 1) * 4;     // 0 or 4
    int brow = tid >> 5;          // 0..7
    int bcol = (tid & 31) * 4;    // 0..124
    int tx = tid & 15, ty = tid >> 4;

    const float* Aptr = A + (size_t)(by * 128 + arow) * K + acol;
    const float* Bptr = B + (size_t)brow * N + bx * 128 + bcol;

    float acc[8][8];
#pragma unroll
    for (int i = 0; i < 8; i++)
#pragma unroll
        for (int j = 0; j < 8; j++) acc[i][j] = 0.f;

    for (int k0 = 0; k0 < K; k0 += 8) {
        float4 av = *(const float4*)Aptr;  Aptr += 8;
        float4 bv = *(const float4*)Bptr;  Bptr += (size_t)8 * N;
        As[acol + 0][arow] = av.x;
        As[acol + 1][arow] = av.y;
        As[acol + 2][arow] = av.z;
        As[acol + 3][arow] = av.w;
        *(float4*)&Bs[brow][bcol] = bv;
        __syncthreads();
#pragma unroll
        for (int kk = 0; kk < 8; kk++) {
            float4 a0 = *(const float4*)&As[kk][ty * 8];
            float4 a1 = *(const float4*)&As[kk][ty * 8 + 4];
            float4 b0 = *(const float4*)&Bs[kk][tx * 8];
            float4 b1 = *(const float4*)&Bs[kk][tx * 8 + 4];
            float ar[8] = {a0.x,a0.y,a0.z,a0.w,a1.x,a1.y,a1.z,a1.w};
            float br[8] = {b0.x,b0.y,b0.z,b0.w,b1.x,b1.y,b1.z,b1.w};
#pragma unroll
            for (int i = 0; i < 8; i++)
#pragma unroll
                for (int j = 0; j < 8; j++)
                    acc[i][j] = fmaf(ar[i], br[j], acc[i][j]);
        }
        __syncthreads();
    }
#pragma unroll
    for (int i = 0; i < 8; i++) {
        size_t crow = (size_t)(by * 128 + ty * 8 + i) * N + bx * 128 + tx * 8;
#pragma unroll
        for (int j = 0; j < 8; j++) {
            float c = acc[i][j];
            if (EPI == 1) c = c / (1.0f + __expf(-c));  // SiLU
            C[crow + j] = c;
        }
    }
}

// ---------------------------------------------------------------------------
// QK^T: S[bh, i, j] = dot(q_i, k_j) / 8 for causal tiles only.
// grid = (T/64 jt, T/64 it, B*H), 256 threads, 64x64 tile, K=HD=64.
// ---------------------------------------------------------------------------
__global__ void __launch_bounds__(256) qk_kernel(
    const float* __restrict__ q, const float* __restrict__ k,
    float* __restrict__ S)
{
    int jt = blockIdx.x, it = blockIdx.y, bh = blockIdx.z;
    if (jt > it) return;  // fully above diagonal
    int b = bh >> 4, h = bh & 15;
    int i0 = it * 64, j0 = jt * 64;
    __shared__ float Qs[64][65];
    __shared__ float Ks[64][65];
    int tid = threadIdx.x;
    int lrow = tid >> 2;           // 0..63
    int lcol = (tid & 3) * 16;     // 0,16,32,48
    const float* qp = q + ((size_t)(b * TT + i0 + lrow) * DD + h * HDD + lcol);
    const float* kp = k + ((size_t)(b * TT + j0 + lrow) * DD + h * HDD + lcol);
#pragma unroll
    for (int v4 = 0; v4 < 4; v4++) {
        float4 qv = *(const float4*)(qp + v4 * 4);
        float4 kv = *(const float4*)(kp + v4 * 4);
        int c = lcol + v4 * 4;
        Qs[lrow][c+0]=qv.x; Qs[lrow][c+1]=qv.y; Qs[lrow][c+2]=qv.z; Qs[lrow][c+3]=qv.w;
        Ks[lrow][c+0]=kv.x; Ks[lrow][c+1]=kv.y; Ks[lrow][c+2]=kv.z; Ks[lrow][c+3]=kv.w;
    }
    __syncthreads();
    int tx = tid & 15, ty = tid >> 4;
    float acc[4][4];
#pragma unroll
    for (int i = 0; i < 4; i++)
#pragma unroll
        for (int j = 0; j < 4; j++) acc[i][j] = 0.f;
#pragma unroll 8
    for (int kk = 0; kk < 64; kk++) {
        float ar[4], br[4];
#pragma unroll
        for (int i = 0; i < 4; i++) ar[i] = Qs[ty * 4 + i][kk];
#pragma unroll
        for (int j = 0; j < 4; j++) br[j] = Ks[tx * 4 + j][kk];
#pragma unroll
        for (int i = 0; i < 4; i++)
#pragma unroll
            for (int j = 0; j < 4; j++)
                acc[i][j] = fmaf(ar[i], br[j], acc[i][j]);
    }
    float* sp = S + ((size_t)bh * TT + i0) * TT + j0;
#pragma unroll
    for (int i = 0; i < 4; i++)
#pragma unroll
        for (int j = 0; j < 4; j++)
            sp[(size_t)(ty * 4 + i) * TT + tx * 4 + j] = acc[i][j] * 0.125f;
}

// ---------------------------------------------------------------------------
// Causal row softmax in-place. grid = B*H*T rows, 128 threads.
// Reads j <= i only; zero-fills (i, tile_end) so PV can run dense per i-tile.
// ---------------------------------------------------------------------------
__global__ void __launch_bounds__(128) softmax_kernel(float* __restrict__ S)
{
    int gr = blockIdx.x;           // bh*T + i
    int i = gr & (TT - 1);
    float* row = S + (size_t)gr * TT;
    int len = i + 1;
    int tid = threadIdx.x;
    float vals[16];
    float m = -1e30f;
#pragma unroll
    for (int t = 0; t < 16; t++) {
        int j = tid + t * 128;
        if (j < len) { vals[t] = row[j]; m = fmaxf(m, vals[t]); }
        else vals[t] = -1e30f;
    }
    __shared__ float red[4];
#pragma unroll
    for (int o = 16; o; o >>= 1) m = fmaxf(m, __shfl_xor_sync(0xffffffffu, m, o));
    if ((tid & 31) == 0) red[tid >> 5] = m;
    __syncthreads();
    float M = fmaxf(fmaxf(red[0], red[1]), fmaxf(red[2], red[3]));
    __syncthreads();
    float s = 0.f;
#pragma unroll
    for (int t = 0; t < 16; t++) {
        float e = __expf(vals[t] - M);
        vals[t] = e;
        s += e;
    }
#pragma unroll
    for (int o = 16; o; o >>= 1) s += __shfl_xor_sync(0xffffffffu, s, o);
    if ((tid & 31) == 0) red[tid >> 5] = s;
    __syncthreads();
    float inv = 1.0f / (red[0] + red[1] + red[2] + red[3]);
    int zend = (i & ~63) + 64;  // zero-fill through the current 64-tile
#pragma unroll
    for (int t = 0; t < 16; t++) {
        int j = tid + t * 128;
        if (j < zend) row[j] = (j < len) ? vals[t] * inv : 0.f;
    }
}

// ---------------------------------------------------------------------------
// PV: ao[bh, i, :] = P[bh, i, 0:i0+64] @ V  (64x64 tile, K bounded causally)
// grid = (T/64 it, B*H), 256 threads.
// ---------------------------------------------------------------------------
__global__ void __launch_bounds__(256) pv_kernel(
    const float* __restrict__ S, const float* __restrict__ v,
    float* __restrict__ ao)
{
    int it = blockIdx.x, bh = blockIdx.y;
    int b = bh >> 4, h = bh & 15;
    int i0 = it * 64;
    __shared__ float Ps[64][65];
    __shared__ float Vs[64][65];
    int tid = threadIdx.x;
    int lrow = tid >> 2, lcol = (tid & 3) * 16;
    int tx = tid & 15, ty = tid >> 4;
    float acc[4][4];
#pragma unroll
    for (int i = 0; i < 4; i++)
#pragma unroll
        for (int j = 0; j < 4; j++) acc[i][j] = 0.f;

    int kend = i0 + 64;
    for (int j0 = 0; j0 < kend; j0 += 64) {
        const float* pp = S + ((size_t)bh * TT + i0 + lrow) * TT + j0 + lcol;
        const float* vp = v + ((size_t)(b * TT + j0 + lrow) * DD + h * HDD + lcol);
#pragma unroll
        for (int v4 = 0; v4 < 4; v4++) {
            float4 pv = *(const float4*)(pp + v4 * 4);
            float4 vv = *(const float4*)(vp + v4 * 4);
            int c = lcol + v4 * 4;
            Ps[lrow][c+0]=pv.x; Ps[lrow][c+1]=pv.y; Ps[lrow][c+2]=pv.z; Ps[lrow][c+3]=pv.w;
            Vs[lrow][c+0]=vv.x; Vs[lrow][c+1]=vv.y; Vs[lrow][c+2]=vv.z; Vs[lrow][c+3]=vv.w;
        }
        __syncthreads();
#pragma unroll 8
        for (int kk = 0; kk < 64; kk++) {
            float ar[4], br[4];
#pragma unroll
            for (int i = 0; i < 4; i++) ar[i] = Ps[ty * 4 + i][kk];
#pragma unroll
            for (int j = 0; j < 4; j++) br[j] = Vs[kk][tx * 4 + j];
#pragma unroll
            for (int i = 0; i < 4; i++)
#pragma unroll
                for (int j = 0; j < 4; j++)
                    acc[i][j] = fmaf(ar[i], br[j], acc[i][j]);
        }
        __syncthreads();
    }
#pragma unroll
    for (int i = 0; i < 4; i++) {
        float* op = ao + (size_t)(b * TT + i0 + ty * 4 + i) * DD + h * HDD + tx * 4;
#pragma unroll
        for (int j = 0; j < 4; j++) op[j] = acc[i][j];
    }
}

// ---------------------------------------------------------------------------
// Launch
// ---------------------------------------------------------------------------
extern "C" void kernel_launch(void* const* d_in, const int* in_sizes, int n_in,
                              void* d_out, int out_size)
{
    const float* x       = (const float*)d_in[0];
    const float* w_pre   = (const float*)d_in[1];
    const float* wq      = (const float*)d_in[2];
    const float* wk      = (const float*)d_in[3];
    const float* wv      = (const float*)d_in[4];
    const float* wo      = (const float*)d_in[5];
    const float* w_attn  = (const float*)d_in[6];
    const float* w1      = (const float*)d_in[7];
    const float* w2      = (const float*)d_in[8];
    const float* w_ffn   = (const float*)d_in[9];
    float* out = (float*)d_out;

    float *h_, *q_, *k_, *v_, *S_, *ao_, *tmp_, *y_, *mid_;
    cudaGetSymbolAddress((void**)&h_,   g_h);
    cudaGetSymbolAddress((void**)&q_,   g_q);
    cudaGetSymbolAddress((void**)&k_,   g_k);
    cudaGetSymbolAddress((void**)&v_,   g_v);
    cudaGetSymbolAddress((void**)&S_,   g_S);
    cudaGetSymbolAddress((void**)&ao_,  g_ao);
    cudaGetSymbolAddress((void**)&tmp_, g_tmp);
    cudaGetSymbolAddress((void**)&y_,   g_y);
    cudaGetSymbolAddress((void**)&mid_, g_mid);

    // 1) h = rmsnorm(x, w_pre)
    rmsnorm_kernel<<<MT, 256>>>(x, nullptr, w_pre, h_);

    // 2) q, k, v projections
    {
        dim3 g(DD / 128, MT / 128);
        sgemm_kernel<0><<<g, 256>>>(h_, wq, q_, MT, DD, DD);
        sgemm_kernel<0><<<g, 256>>>(h_, wk, k_, MT, DD, DD);
        sgemm_kernel<0><<<g, 256>>>(h_, wv, v_, MT, DD, DD);
    }

    // 3) scores (causal tiles), softmax, PV
    {
        dim3 g(TT / 64, TT / 64, BB * HH);
        qk_kernel<<<g, 256>>>(q_, k_, S_);
    }
    softmax_kernel<<<BB * HH * TT, 128>>>(S_);
    {
        dim3 g(TT / 64, BB * HH);
        pv_kernel<<<g, 256>>>(S_, v_, ao_);
    }

    // 4) o-projection + residual norm: y = rmsnorm(h + ao@wo, w_attn)
    {
        dim3 g(DD / 128, MT / 128);
        sgemm_kernel<0><<<g, 256>>>(ao_, wo, tmp_, MT, DD, DD);
    }
    rmsnorm_kernel<<<MT, 256>>>(h_, tmp_, w_attn, y_);

    // 5) FFN: mid = silu(y@w1); f = mid@w2; out = rmsnorm(y + f, w_ffn)
    {
        dim3 g(FFD / 128, MT / 128);
        sgemm_kernel<1><<<g, 256>>>(y_, w1, mid_, MT, FFD, DD);
    }
    {
        dim3 g(DD / 128, MT / 128);
        sgemm_kernel<0><<<g, 256>>>(mid_, w2, tmp_, MT, DD, FFD);
    }
    rmsnorm_kernel<<<MT, 256>>>(y_, tmp_, w_ffn, out);
}

// round 2
// speedup vs baseline: 2.9731x; 2.9731x over previous
#include <cuda_runtime.h>
#include <cstdint>
#include <cstddef>

#define BB   2
#define TT   2048
#define DD   1024
#define HH   16
#define HDD  64
#define FFD  4096
#define MT   (BB*TT)

// ---------------------------------------------------------------------------
// Scratch
// ---------------------------------------------------------------------------
__device__ float g_h  [MT*DD];
__device__ float g_q  [MT*DD];
__device__ float g_k  [MT*DD];
__device__ float g_v  [MT*DD];
__device__ float g_S  [(size_t)BB*HH*TT*TT];
__device__ float g_ao [MT*DD];
__device__ float g_tmp[MT*DD];
__device__ float g_y  [MT*DD];
__device__ float g_mid[MT*FFD];
__device__ float g_w  [12*1024*1024];   // tf32-rounded weights

#define WQ_OFF 0
#define WK_OFF (1024*1024)
#define WV_OFF (2*1024*1024)
#define WO_OFF (3*1024*1024)
#define W1_OFF (4*1024*1024)
#define W2_OFF (8*1024*1024)

// ---------------------------------------------------------------------------
// Helpers
// ---------------------------------------------------------------------------
__device__ __forceinline__ float tf32r(float x) {
    float r; asm("cvt.rna.tf32.f32 %0, %1;" : "=f"(r) : "f"(x)); return r;
}
__device__ __forceinline__ uint32_t smaddr(const void* p) {
    return (uint32_t)__cvta_generic_to_shared(p);
}
#define CP16(dst, src) asm volatile("cp.async.cg.shared.global [%0], [%1], 16;\n" :: "r"(dst), "l"(src))
#define CP_COMMIT()    asm volatile("cp.async.commit_group;\n")

// D += A(16x8) * B(8x8), tf32
__device__ __forceinline__ void mma8(float* d, const float* a, const float* b) {
    asm volatile(
        "mma.sync.aligned.m16n8k8.row.col.f32.tf32.tf32.f32 "
        "{%0,%1,%2,%3}, {%4,%5,%6,%7}, {%8,%9}, {%0,%1,%2,%3};\n"
        : "+f"(d[0]), "+f"(d[1]), "+f"(d[2]), "+f"(d[3])
        : "r"(__float_as_uint(a[0])), "r"(__float_as_uint(a[1])),
          "r"(__float_as_uint(a[2])), "r"(__float_as_uint(a[3])),
          "r"(__float_as_uint(b[0])), "r"(__float_as_uint(b[1])));
}

// ---------------------------------------------------------------------------
// Round a tensor to tf32 (vectorized)
// ---------------------------------------------------------------------------
__global__ void __launch_bounds__(256) round4_kernel(
    const float4* __restrict__ in, float4* __restrict__ out, int n4)
{
    int i = blockIdx.x * 256 + threadIdx.x;
    if (i < n4) {
        float4 v = in[i];
        v.x = tf32r(v.x); v.y = tf32r(v.y); v.z = tf32r(v.z); v.w = tf32r(v.w);
        out[i] = v;
    }
}

// ---------------------------------------------------------------------------
// RMSNorm (optionally + residual); RND: round output to tf32
// ---------------------------------------------------------------------------
template <int RND>
__global__ void __launch_bounds__(256) rmsnorm_kernel(
    const float* __restrict__ a, const float* __restrict__ b,
    const float* __restrict__ w, float* __restrict__ out)
{
    int row = blockIdx.x;
    size_t base = (size_t)row * DD;
    float v[4];
    float ss = 0.f;
#pragma unroll
    for (int t = 0; t < 4; t++) {
        int c = threadIdx.x + t * 256;
        float x = a[base + c];
        if (b) x += b[base + c];
        v[t] = x;
        ss += x * x;
    }
    __shared__ float red[8];
#pragma unroll
    for (int o = 16; o; o >>= 1) ss += __shfl_xor_sync(0xffffffffu, ss, o);
    if ((threadIdx.x & 31) == 0) red[threadIdx.x >> 5] = ss;
    __syncthreads();
    if (threadIdx.x == 0) {
        float tot = 0.f;
#pragma unroll
        for (int i = 0; i < 8; i++) tot += red[i];
        red[0] = tot;
    }
    __syncthreads();
    float scale = rsqrtf(red[0] * (1.0f / DD) + 1e-6f);
#pragma unroll
    for (int t = 0; t < 4; t++) {
        int c = threadIdx.x + t * 256;
        float o = v[t] * scale * w[c];
        out[base + c] = RND ? tf32r(o) : o;
    }
}

// ---------------------------------------------------------------------------
// TF32 tensor-core GEMM: C[M,N] = A[M,K] @ B[K,N] (row-major, tf32-rounded in)
// BM=BN=128, BK=16, 256 threads (8 warps x 64x32), double-buffered cp.async.
// EPI: 0 none, 1 SiLU.  RND: round output to tf32.
// ---------------------------------------------------------------------------
template <int EPI, int RND>
__global__ void __launch_bounds__(256, 2) tgemm_kernel(
    const float* __restrict__ A, const float* __restrict__ B,
    float* __restrict__ C, int M, int N, int K)
{
    __shared__ float As[2][128 * 20];   // [m][k], stride 20 (conflict-free frags)
    __shared__ float Bs[2][16 * 136];   // [k][n], stride 136 (==8 mod 32)

    int tid = threadIdx.x;
    int warp = tid >> 5, lane = tid & 31;
    int g = lane >> 2, tig = lane & 3;
    int wm = (warp >> 2) * 64, wn = (warp & 3) * 32;
    int bx = blockIdx.x, by = blockIdx.y;

    // gmem->smem assignment
    int ar = tid >> 2;            // A rows ar, ar+64
    int ac = (tid & 3) * 4;       // A k-cols {0,4,8,12}
    int br = tid >> 5;            // B k-rows br, br+8
    int bc = lane * 4;            // B n-cols

    const float* a_src = A + (size_t)(by * 128 + ar) * K + ac;
    const float* b_src = B + (size_t)br * N + bx * 128 + bc;
    uint32_t a_dst = smaddr(&As[0][ar * 20 + ac]);
    uint32_t b_dst = smaddr(&Bs[0][br * 136 + bc]);

    float acc[4][4][4];
#pragma unroll
    for (int i = 0; i < 4; i++)
#pragma unroll
        for (int j = 0; j < 4; j++)
#pragma unroll
            for (int r = 0; r < 4; r++) acc[i][j][r] = 0.f;

    int KT = K >> 4;

    // prologue: stage 0
    {
        CP16(a_dst, a_src);
        CP16(a_dst + 5120, a_src + (size_t)64 * K);
        CP16(b_dst, b_src);
        CP16(b_dst + 4352, b_src + (size_t)8 * N);
        CP_COMMIT();
    }

    for (int kt = 0; kt < KT; kt++) {
        int buf = kt & 1;
        if (kt + 1 < KT) {
            int k0 = (kt + 1) << 4;
            uint32_t ad = a_dst + (buf ^ 1) * 10240;
            const float* as_ = a_src + k0;
            CP16(ad, as_);
            CP16(ad + 5120, as_ + (size_t)64 * K);
            uint32_t bd = b_dst + (buf ^ 1) * 8704;
            const float* bs_ = b_src + (size_t)k0 * N;
            CP16(bd, bs_);
            CP16(bd + 4352, bs_ + (size_t)8 * N);
            CP_COMMIT();
            asm volatile("cp.async.wait_group 1;\n");
        } else {
            asm volatile("cp.async.wait_group 0;\n");
        }
        __syncthreads();

        const float* as = As[buf];
        const float* bs = Bs[buf];
#pragma unroll
        for (int ch = 0; ch < 2; ch++) {
            int kb = ch * 8 + tig;
            float a[4][4], b[4][2];
#pragma unroll
            for (int mt = 0; mt < 4; mt++) {
                int m = wm + mt * 16 + g;
                a[mt][0] = as[m * 20 + kb];
                a[mt][1] = as[(m + 8) * 20 + kb];
                a[mt][2] = as[m * 20 + kb + 4];
                a[mt][3] = as[(m + 8) * 20 + kb + 4];
            }
#pragma unroll
            for (int nt = 0; nt < 4; nt++) {
                int n = wn + nt * 8 + g;
                b[nt][0] = bs[kb * 136 + n];
                b[nt][1] = bs[(kb + 4) * 136 + n];
            }
#pragma unroll
            for (int mt = 0; mt < 4; mt++)
#pragma unroll
                for (int nt = 0; nt < 4; nt++) mma8(acc[mt][nt], a[mt], b[nt]);
        }
        __syncthreads();
    }

    // epilogue
#pragma unroll
    for (int mt = 0; mt < 4; mt++) {
#pragma unroll
        for (int nt = 0; nt < 4; nt++) {
            int row = by * 128 + wm + mt * 16 + g;
            int col = bx * 128 + wn + nt * 8 + 2 * tig;
            float e[4];
#pragma unroll
            for (int r = 0; r < 4; r++) {
                float c = acc[mt][nt][r];
                if (EPI == 1) c = c / (1.0f + __expf(-c));
                if (RND)      c = tf32r(c);
                e[r] = c;
            }
            *(float2*)&C[(size_t)row * N + col]       = make_float2(e[0], e[1]);
            *(float2*)&C[(size_t)(row + 8) * N + col] = make_float2(e[2], e[3]);
        }
    }
}

// ---------------------------------------------------------------------------
// QK^T (tf32 mma): 64x64 tile per block, K=HD=64, causal tiles only
// ---------------------------------------------------------------------------
__global__ void __launch_bounds__(256) qk_mma_kernel(
    const float* __restrict__ q, const float* __restrict__ k,
    float* __restrict__ S)
{
    int jt = blockIdx.x, it = blockIdx.y, bh = blockIdx.z;
    if (jt > it) return;
    int b = bh >> 4, h = bh & 15;
    __shared__ float Qs[64 * 68];
    __shared__ float Ks[64 * 68];

    int tid = threadIdx.x, warp = tid >> 5, lane = tid & 31;
    int g = lane >> 2, tig = lane & 3;
    int wm = (warp >> 1) * 16, wn = (warp & 1) * 32;

    int lr = tid >> 2, lc = (tid & 3) * 4;
    const float* qp = q + (size_t)(b * TT + it * 64 + lr) * DD + h * HDD;
    const float* kp = k + (size_t)(b * TT + jt * 64 + lr) * DD + h * HDD;
#pragma unroll
    for (int r = 0; r < 4; r++) {
        *(float4*)&Qs[lr * 68 + lc + r * 16] = *(const float4*)(qp + lc + r * 16);
        *(float4*)&Ks[lr * 68 + lc + r * 16] = *(const float4*)(kp + lc + r * 16);
    }
    __syncthreads();

    float acc[4][4];
#pragma unroll
    for (int nt = 0; nt < 4; nt++)
#pragma unroll
        for (int r = 0; r < 4; r++) acc[nt][r] = 0.f;

#pragma unroll
    for (int ch = 0; ch < 8; ch++) {
        int kb = ch * 8 + tig;
        int m = wm + g;
        float a[4];
        a[0] = Qs[m * 68 + kb];
        a[1] = Qs[(m + 8) * 68 + kb];
        a[2] = Qs[m * 68 + kb + 4];
        a[3] = Qs[(m + 8) * 68 + kb + 4];
#pragma unroll
        for (int nt = 0; nt < 4; nt++) {
            int n = wn + nt * 8 + g;
            float bfr[2] = { Ks[n * 68 + kb], Ks[n * 68 + kb + 4] };
            mma8(acc[nt], a, bfr);
        }
    }

    float* sp = S + ((size_t)bh * TT + it * 64) * TT + jt * 64;
#pragma unroll
    for (int nt = 0; nt < 4; nt++) {
        int row = wm + g;
        int col = wn + nt * 8 + 2 * tig;
        *(float2*)&sp[(size_t)row * TT + col] =
            make_float2(acc[nt][0] * 0.125f, acc[nt][1] * 0.125f);
        *(float2*)&sp[(size_t)(row + 8) * TT + col] =
            make_float2(acc[nt][2] * 0.125f, acc[nt][3] * 0.125f);
    }
}

// ---------------------------------------------------------------------------
// Causal row softmax; writes tf32-rounded probs, zero-fills to tile end
// ---------------------------------------------------------------------------
__global__ void __launch_bounds__(128) softmax_kernel(float* __restrict__ S)
{
    int gr = blockIdx.x;
    int i = gr & (TT - 1);
    float* row = S + (size_t)gr * TT;
    int len = i + 1;
    int tid = threadIdx.x;
    float vals[16];
    float m = -1e30f;
#pragma unroll
    for (int t = 0; t < 16; t++) {
        int j = tid + t * 128;
        if (j < len) { vals[t] = row[j]; m = fmaxf(m, vals[t]); }
        else vals[t] = -1e30f;
    }
    __shared__ float red[4];
#pragma unroll
    for (int o = 16; o; o >>= 1) m = fmaxf(m, __shfl_xor_sync(0xffffffffu, m, o));
    if ((tid & 31) == 0) red[tid >> 5] = m;
    __syncthreads();
    float M = fmaxf(fmaxf(red[0], red[1]), fmaxf(red[2], red[3]));
    __syncthreads();
    float s = 0.f;
#pragma unroll
    for (int t = 0; t < 16; t++) {
        float e = __expf(vals[t] - M);
        vals[t] = e;
        s += e;
    }
#pragma unroll
    for (int o = 16; o; o >>= 1) s += __shfl_xor_sync(0xffffffffu, s, o);
    if ((tid & 31) == 0) red[tid >> 5] = s;
    __syncthreads();
    float inv = 1.0f / (red[0] + red[1] + red[2] + red[3]);
    int zend = (i & ~63) + 64;
#pragma unroll
    for (int t = 0; t < 16; t++) {
        int j = tid + t * 128;
        if (j < zend) row[j] = (j < len) ? tf32r(vals[t] * inv) : 0.f;
    }
}

// ---------------------------------------------------------------------------
// PV (tf32 mma): 64x64 out tile, K over causal j-tiles
// ---------------------------------------------------------------------------
__global__ void __launch_bounds__(256) pv_mma_kernel(
    const float* __restrict__ S, const float* __restrict__ v,
    float* __restrict__ ao)
{
    int it = blockIdx.x, bh = blockIdx.y;
    int b = bh >> 4, h = bh & 15;
    __shared__ float Ps[64 * 68];
    __shared__ float Vs[64 * 72];

    int tid = threadIdx.x, warp = tid >> 5, lane = tid & 31;
    int g = lane >> 2, tig = lane & 3;
    int wm = (warp >> 1) * 16, wn = (warp & 1) * 32;
    int lr = tid >> 2, lc = (tid & 3) * 4;

    float acc[4][4];
#pragma unroll
    for (int nt = 0; nt < 4; nt++)
#pragma unroll
        for (int r = 0; r < 4; r++) acc[nt][r] = 0.f;

    const float* prow = S + ((size_t)bh * TT + it * 64 + lr) * TT;
    for (int j0 = 0; j0 <= it * 64; j0 += 64) {
        const float* pp = prow + j0;
        const float* vp = v + (size_t)(b * TT + j0 + lr) * DD + h * HDD;
#pragma unroll
        for (int r = 0; r < 4; r++) {
            *(float4*)&Ps[lr * 68 + lc + r * 16] = *(const float4*)(pp + lc + r * 16);
            *(float4*)&Vs[lr * 72 + lc + r * 16] = *(const float4*)(vp + lc + r * 16);
        }
        __syncthreads();
#pragma unroll
        for (int ch = 0; ch < 8; ch++) {
            int kb = ch * 8 + tig;
            int m = wm + g;
            float a[4];
            a[0] = Ps[m * 68 + kb];
            a[1] = Ps[(m + 8) * 68 + kb];
            a[2] = Ps[m * 68 + kb + 4];
            a[3] = Ps[(m + 8) * 68 + kb + 4];
#pragma unroll
            for (int nt = 0; nt < 4; nt++) {
                int n = wn + nt * 8 + g;
                float bfr[2] = { Vs[kb * 72 + n], Vs[(kb + 4) * 72 + n] };
                mma8(acc[nt], a, bfr);
            }
        }
        __syncthreads();
    }

#pragma unroll
    for (int nt = 0; nt < 4; nt++) {
        int row = wm + g;
        int col = wn + nt * 8 + 2 * tig;
        float* op0 = ao + (size_t)(b * TT + it * 64 + row) * DD + h * HDD + col;
        float* op1 = ao + (size_t)(b * TT + it * 64 + row + 8) * DD + h * HDD + col;
        *(float2*)op0 = make_float2(tf32r(acc[nt][0]), tf32r(acc[nt][1]));
        *(float2*)op1 = make_float2(tf32r(acc[nt][2]), tf32r(acc[nt][3]));
    }
}

// ---------------------------------------------------------------------------
// Launch
// ---------------------------------------------------------------------------
extern "C" void kernel_launch(void* const* d_in, const int* in_sizes, int n_in,
                              void* d_out, int out_size)
{
    const float* x      = (const float*)d_in[0];
    const float* w_pre  = (const float*)d_in[1];
    const float* wq     = (const float*)d_in[2];
    const float* wk     = (const float*)d_in[3];
    const float* wv     = (const float*)d_in[4];
    const float* wo     = (const float*)d_in[5];
    const float* w_attn = (const float*)d_in[6];
    const float* w1     = (const float*)d_in[7];
    const float* w2     = (const float*)d_in[8];
    const float* w_ffn  = (const float*)d_in[9];
    float* out = (float*)d_out;

    float *h_, *q_, *k_, *v_, *S_, *ao_, *tmp_, *y_, *mid_, *w_;
    cudaGetSymbolAddress((void**)&h_,   g_h);
    cudaGetSymbolAddress((void**)&q_,   g_q);
    cudaGetSymbolAddress((void**)&k_,   g_k);
    cudaGetSymbolAddress((void**)&v_,   g_v);
    cudaGetSymbolAddress((void**)&S_,   g_S);
    cudaGetSymbolAddress((void**)&ao_,  g_ao);
    cudaGetSymbolAddress((void**)&tmp_, g_tmp);
    cudaGetSymbolAddress((void**)&y_,   g_y);
    cudaGetSymbolAddress((void**)&mid_, g_mid);
    cudaGetSymbolAddress((void**)&w_,   g_w);

    // 0) round weights to tf32 once (lossless re-round on replay)
    round4_kernel<<<(DD*DD/4 + 255)/256, 256>>>((const float4*)wq, (float4*)(w_ + WQ_OFF), DD*DD/4);
    round4_kernel<<<(DD*DD/4 + 255)/256, 256>>>((const float4*)wk, (float4*)(w_ + WK_OFF), DD*DD/4);
    round4_kernel<<<(DD*DD/4 + 255)/256, 256>>>((const float4*)wv, (float4*)(w_ + WV_OFF), DD*DD/4);
    round4_kernel<<<(DD*DD/4 + 255)/256, 256>>>((const float4*)wo, (float4*)(w_ + WO_OFF), DD*DD/4);
    round4_kernel<<<(DD*FFD/4 + 255)/256, 256>>>((const float4*)w1, (float4*)(w_ + W1_OFF), DD*FFD/4);
    round4_kernel<<<(DD*FFD/4 + 255)/256, 256>>>((const float4*)w2, (float4*)(w_ + W2_OFF), DD*FFD/4);

    // 1) h = rmsnorm(x) (tf32-rounded output)
    rmsnorm_kernel<1><<<MT, 256>>>(x, nullptr, w_pre, h_);

    // 2) q, k, v projections (round outputs for attention mma)
    {
        dim3 g(DD / 128, MT / 128);
        tgemm_kernel<0, 1><<<g, 256>>>(h_, w_ + WQ_OFF, q_, MT, DD, DD);
        tgemm_kernel<0, 1><<<g, 256>>>(h_, w_ + WK_OFF, k_, MT, DD, DD);
        tgemm_kernel<0, 1><<<g, 256>>>(h_, w_ + WV_OFF, v_, MT, DD, DD);
    }

    // 3) attention
    {
        dim3 g(TT / 64, TT / 64, BB * HH);
        qk_mma_kernel<<<g, 256>>>(q_, k_, S_);
    }
    softmax_kernel<<<BB * HH * TT, 128>>>(S_);
    {
        dim3 g(TT / 64, BB * HH);
        pv_mma_kernel<<<g, 256>>>(S_, v_, ao_);
    }

    // 4) o-proj + residual norm
    {
        dim3 g(DD / 128, MT / 128);
        tgemm_kernel<0, 0><<<g, 256>>>(ao_, w_ + WO_OFF, tmp_, MT, DD, DD);
    }
    rmsnorm_kernel<1><<<MT, 256>>>(h_, tmp_, w_attn, y_);

    // 5) FFN
    {
        dim3 g(FFD / 128, MT / 128);
        tgemm_kernel<1, 1><<<g, 256>>>(y_, w_ + W1_OFF, mid_, MT, FFD, DD);
    }
    {
        dim3 g(DD / 128, MT / 128);
        tgemm_kernel<0, 0><<<g, 256>>>(mid_, w_ + W2_OFF, tmp_, MT, DD, FFD);
    }
    rmsnorm_kernel<0><<<MT, 256>>>(y_, tmp_, w_ffn, out);
}

// round 3
// speedup vs baseline: 3.4987x; 1.1768x over previous
#include <cuda_runtime.h>
#include <cstdint>
#include <cstddef>

#define BB   2
#define TT   2048
#define DD   1024
#define HH   16
#define HDD  64
#define FFD  4096
#define MT   (BB*TT)

// ---------------------------------------------------------------------------
// Scratch
// ---------------------------------------------------------------------------
__device__ float g_h  [MT*DD];
__device__ float g_q  [MT*DD];
__device__ float g_k  [MT*DD];
__device__ float g_v  [MT*DD];
__device__ float g_ao [MT*DD];
__device__ float g_tmp[MT*DD];
__device__ float g_y  [MT*DD];
__device__ float g_mid[MT*FFD];
__device__ float g_w  [12*1024*1024];   // tf32-rounded weights

#define WQ_OFF 0
#define WK_OFF (1024*1024)
#define WV_OFF (2*1024*1024)
#define WO_OFF (3*1024*1024)
#define W1_OFF (4*1024*1024)
#define W2_OFF (8*1024*1024)

// ---------------------------------------------------------------------------
// Helpers
// ---------------------------------------------------------------------------
__device__ __forceinline__ float tf32r(float x) {
    float r; asm("cvt.rna.tf32.f32 %0, %1;" : "=f"(r) : "f"(x)); return r;
}
__device__ __forceinline__ uint32_t smaddr(const void* p) {
    return (uint32_t)__cvta_generic_to_shared(p);
}
#define CP16(dst, src) asm volatile("cp.async.cg.shared.global [%0], [%1], 16;\n" :: "r"(dst), "l"(src))
#define CP_COMMIT()    asm volatile("cp.async.commit_group;\n")

// D += A(16x8) * B(8x8), tf32
__device__ __forceinline__ void mma8(float* d, const float* a, const float* b) {
    asm volatile(
        "mma.sync.aligned.m16n8k8.row.col.f32.tf32.tf32.f32 "
        "{%0,%1,%2,%3}, {%4,%5,%6,%7}, {%8,%9}, {%0,%1,%2,%3};\n"
        : "+f"(d[0]), "+f"(d[1]), "+f"(d[2]), "+f"(d[3])
        : "r"(__float_as_uint(a[0])), "r"(__float_as_uint(a[1])),
          "r"(__float_as_uint(a[2])), "r"(__float_as_uint(a[3])),
          "r"(__float_as_uint(b[0])), "r"(__float_as_uint(b[1])));
}

// ---------------------------------------------------------------------------
// Round a tensor to tf32 (vectorized)
// ---------------------------------------------------------------------------
__global__ void __launch_bounds__(256) round4_kernel(
    const float4* __restrict__ in, float4* __restrict__ out, int n4)
{
    int i = blockIdx.x * 256 + threadIdx.x;
    if (i < n4) {
        float4 v = in[i];
        v.x = tf32r(v.x); v.y = tf32r(v.y); v.z = tf32r(v.z); v.w = tf32r(v.w);
        out[i] = v;
    }
}

// ---------------------------------------------------------------------------
// RMSNorm (optionally + residual); RND: round output to tf32
// ---------------------------------------------------------------------------
template <int RND>
__global__ void __launch_bounds__(256) rmsnorm_kernel(
    const float* __restrict__ a, const float* __restrict__ b,
    const float* __restrict__ w, float* __restrict__ out)
{
    int row = blockIdx.x;
    size_t base = (size_t)row * DD;
    float v[4];
    float ss = 0.f;
#pragma unroll
    for (int t = 0; t < 4; t++) {
        int c = threadIdx.x + t * 256;
        float x = a[base + c];
        if (b) x += b[base + c];
        v[t] = x;
        ss += x * x;
    }
    __shared__ float red[8];
#pragma unroll
    for (int o = 16; o; o >>= 1) ss += __shfl_xor_sync(0xffffffffu, ss, o);
    if ((threadIdx.x & 31) == 0) red[threadIdx.x >> 5] = ss;
    __syncthreads();
    if (threadIdx.x == 0) {
        float tot = 0.f;
#pragma unroll
        for (int i = 0; i < 8; i++) tot += red[i];
        red[0] = tot;
    }
    __syncthreads();
    float scale = rsqrtf(red[0] * (1.0f / DD) + 1e-6f);
#pragma unroll
    for (int t = 0; t < 4; t++) {
        int c = threadIdx.x + t * 256;
        float o = v[t] * scale * w[c];
        out[base + c] = RND ? tf32r(o) : o;
    }
}

// ---------------------------------------------------------------------------
// TF32 tensor-core GEMM (as round 2): BM=BN=128, BK=16, 256 thr, dbl-buffer
// ---------------------------------------------------------------------------
template <int EPI, int RND>
__global__ void __launch_bounds__(256, 2) tgemm_kernel(
    const float* __restrict__ A, const float* __restrict__ B,
    float* __restrict__ C, int M, int N, int K)
{
    __shared__ float As[2][128 * 20];
    __shared__ float Bs[2][16 * 136];

    int tid = threadIdx.x;
    int warp = tid >> 5, lane = tid & 31;
    int g = lane >> 2, tig = lane & 3;
    int wm = (warp >> 2) * 64, wn = (warp & 3) * 32;
    int bx = blockIdx.x, by = blockIdx.y;

    int ar = tid >> 2;
    int ac = (tid & 3) * 4;
    int br = tid >> 5;
    int bc = lane * 4;

    const float* a_src = A + (size_t)(by * 128 + ar) * K + ac;
    const float* b_src = B + (size_t)br * N + bx * 128 + bc;
    uint32_t a_dst = smaddr(&As[0][ar * 20 + ac]);
    uint32_t b_dst = smaddr(&Bs[0][br * 136 + bc]);

    float acc[4][4][4];
#pragma unroll
    for (int i = 0; i < 4; i++)
#pragma unroll
        for (int j = 0; j < 4; j++)
#pragma unroll
            for (int r = 0; r < 4; r++) acc[i][j][r] = 0.f;

    int KT = K >> 4;
    {
        CP16(a_dst, a_src);
        CP16(a_dst + 5120, a_src + (size_t)64 * K);
        CP16(b_dst, b_src);
        CP16(b_dst + 4352, b_src + (size_t)8 * N);
        CP_COMMIT();
    }

    for (int kt = 0; kt < KT; kt++) {
        int buf = kt & 1;
        if (kt + 1 < KT) {
            int k0 = (kt + 1) << 4;
            uint32_t ad = a_dst + (buf ^ 1) * 10240;
            const float* as_ = a_src + k0;
            CP16(ad, as_);
            CP16(ad + 5120, as_ + (size_t)64 * K);
            uint32_t bd = b_dst + (buf ^ 1) * 8704;
            const float* bs_ = b_src + (size_t)k0 * N;
            CP16(bd, bs_);
            CP16(bd + 4352, bs_ + (size_t)8 * N);
            CP_COMMIT();
            asm volatile("cp.async.wait_group 1;\n");
        } else {
            asm volatile("cp.async.wait_group 0;\n");
        }
        __syncthreads();

        const float* as = As[buf];
        const float* bs = Bs[buf];
#pragma unroll
        for (int ch = 0; ch < 2; ch++) {
            int kb = ch * 8 + tig;
            float a[4][4], b[4][2];
#pragma unroll
            for (int mt = 0; mt < 4; mt++) {
                int m = wm + mt * 16 + g;
                a[mt][0] = as[m * 20 + kb];
                a[mt][1] = as[(m + 8) * 20 + kb];
                a[mt][2] = as[m * 20 + kb + 4];
                a[mt][3] = as[(m + 8) * 20 + kb + 4];
            }
#pragma unroll
            for (int nt = 0; nt < 4; nt++) {
                int n = wn + nt * 8 + g;
                b[nt][0] = bs[kb * 136 + n];
                b[nt][1] = bs[(kb + 4) * 136 + n];
            }
#pragma unroll
            for (int mt = 0; mt < 4; mt++)
#pragma unroll
                for (int nt = 0; nt < 4; nt++) mma8(acc[mt][nt], a[mt], b[nt]);
        }
        __syncthreads();
    }

#pragma unroll
    for (int mt = 0; mt < 4; mt++) {
#pragma unroll
        for (int nt = 0; nt < 4; nt++) {
            int row = by * 128 + wm + mt * 16 + g;
            int col = bx * 128 + wn + nt * 8 + 2 * tig;
            float e[4];
#pragma unroll
            for (int r = 0; r < 4; r++) {
                float c = acc[mt][nt][r];
                if (EPI == 1) c = c / (1.0f + __expf(-c));
                if (RND)      c = tf32r(c);
                e[r] = c;
            }
            *(float2*)&C[(size_t)row * N + col]       = make_float2(e[0], e[1]);
            *(float2*)&C[(size_t)(row + 8) * N + col] = make_float2(e[2], e[3]);
        }
    }
}

// ---------------------------------------------------------------------------
// Flash attention: per block = (128 q-rows, one head). Online softmax.
// 8 warps; warp w owns q rows [w*16, w*16+16). K/V stream through smem in
// 64-row tiles. P re-laid out C-frag -> A-frag via warp shuffles.
// ---------------------------------------------------------------------------
__global__ void __launch_bounds__(256) flash_kernel(
    const float* __restrict__ q, const float* __restrict__ k,
    const float* __restrict__ v, float* __restrict__ ao)
{
    int it = blockIdx.x;            // 0..15
    int bh = blockIdx.y;            // 0..31
    int b = bh >> 4, h = bh & 15;
    int i0 = it * 128;

    __shared__ float smem[64 * 68 + 64 * 72];  // 35.8 KB
    float* Ks = smem;          // [64][68]
    float* Vs = smem + 64 * 68; // [64][72]
    float* Qstage = smem;      // aliased during prologue (needs 128*68=8704 floats <= 9.0K)

    int tid = threadIdx.x, warp = tid >> 5, lane = tid & 31;
    int g = lane >> 2, tig = lane & 3;

    // ---- stage Q tile (128 x 64) into smem, then to register A-frags ----
    {
        int r = tid >> 1;
        int cb = (tid & 1) * 32;
        const float* qp = q + (size_t)(b * TT + i0 + r) * DD + h * HDD + cb;
        float* dst = Qstage + r * 68 + cb;
#pragma unroll
        for (int c4 = 0; c4 < 8; c4++)
            *(float4*)(dst + c4 * 4) = *(const float4*)(qp + c4 * 4);
    }
    __syncthreads();
    float qa[8][4];
    {
        int m = warp * 16 + g;
#pragma unroll
        for (int kt = 0; kt < 8; kt++) {
            int kb = kt * 8 + tig;
            qa[kt][0] = Qstage[m * 68 + kb] * 0.125f;        // fold 1/sqrt(64)
            qa[kt][1] = Qstage[(m + 8) * 68 + kb] * 0.125f;  // (power of 2: tf32-exact)
            qa[kt][2] = Qstage[m * 68 + kb + 4] * 0.125f;
            qa[kt][3] = Qstage[(m + 8) * 68 + kb + 4] * 0.125f;
        }
    }
    __syncthreads();

    float o[8][4];
#pragma unroll
    for (int nt = 0; nt < 8; nt++)
#pragma unroll
        for (int r = 0; r < 4; r++) o[nt][r] = 0.f;
    float rm0 = -1e30f, rm1 = -1e30f, rs0 = 0.f, rs1 = 0.f;

    int jt_max = 2 * it + 1;
    int warp_row0 = i0 + warp * 16;
    int src0 = g * 4 + (tig >> 1);
    int src1 = src0 + 2;
    bool hi = tig & 1;

    for (int jt = 0; jt <= jt_max; jt++) {
        int j0 = jt * 64;
        // load K, V tiles (64 x 64)
        {
            int r = tid >> 2, cb = (tid & 3) * 16;
            const float* kp = k + (size_t)(b * TT + j0 + r) * DD + h * HDD + cb;
            const float* vp = v + (size_t)(b * TT + j0 + r) * DD + h * HDD + cb;
#pragma unroll
            for (int c4 = 0; c4 < 4; c4++) {
                *(float4*)(Ks + r * 68 + cb + c4 * 4) = *(const float4*)(kp + c4 * 4);
                *(float4*)(Vs + r * 72 + cb + c4 * 4) = *(const float4*)(vp + c4 * 4);
            }
        }
        __syncthreads();

        if (j0 <= warp_row0 + 15) {   // tile touches valid region for this warp
            // ---- S = Q K^T / 8 ----
            float s[8][4];
#pragma unroll
            for (int nt = 0; nt < 8; nt++)
#pragma unroll
                for (int r = 0; r < 4; r++) s[nt][r] = 0.f;
#pragma unroll
            for (int kt = 0; kt < 8; kt++) {
                int kb = kt * 8 + tig;
#pragma unroll
                for (int nt = 0; nt < 8; nt++) {
                    float bfr[2] = { Ks[(nt * 8 + g) * 68 + kb],
                                     Ks[(nt * 8 + g) * 68 + kb + 4] };
                    mma8(s[nt], qa[kt], bfr);
                }
            }
            // ---- causal mask (only partial tiles) ----
            int r0 = warp_row0 + g, r1 = r0 + 8;
            if (j0 + 63 > warp_row0) {
#pragma unroll
                for (int nt = 0; nt < 8; nt++) {
                    int j = j0 + nt * 8 + 2 * tig;
                    if (j     > r0) s[nt][0] = -1e30f;
                    if (j + 1 > r0) s[nt][1] = -1e30f;
                    if (j     > r1) s[nt][2] = -1e30f;
                    if (j + 1 > r1) s[nt][3] = -1e30f;
                }
            }
            // ---- online softmax ----
            float m0 = -1e30f, m1 = -1e30f;
#pragma unroll
            for (int nt = 0; nt < 8; nt++) {
                m0 = fmaxf(m0, fmaxf(s[nt][0], s[nt][1]));
                m1 = fmaxf(m1, fmaxf(s[nt][2], s[nt][3]));
            }
            m0 = fmaxf(m0, __shfl_xor_sync(0xffffffffu, m0, 1));
            m0 = fmaxf(m0, __shfl_xor_sync(0xffffffffu, m0, 2));
            m1 = fmaxf(m1, __shfl_xor_sync(0xffffffffu, m1, 1));
            m1 = fmaxf(m1, __shfl_xor_sync(0xffffffffu, m1, 2));
            float nm0 = fmaxf(rm0, m0), nm1 = fmaxf(rm1, m1);
            float al0 = __expf(rm0 - nm0), al1 = __expf(rm1 - nm1);
            rm0 = nm0; rm1 = nm1;
            float l0 = 0.f, l1 = 0.f;
#pragma unroll
            for (int nt = 0; nt < 8; nt++) {
                s[nt][0] = tf32r(__expf(s[nt][0] - nm0));
                s[nt][1] = tf32r(__expf(s[nt][1] - nm0));
                s[nt][2] = tf32r(__expf(s[nt][2] - nm1));
                s[nt][3] = tf32r(__expf(s[nt][3] - nm1));
                l0 += s[nt][0] + s[nt][1];
                l1 += s[nt][2] + s[nt][3];
            }
            l0 += __shfl_xor_sync(0xffffffffu, l0, 1);
            l0 += __shfl_xor_sync(0xffffffffu, l0, 2);
            l1 += __shfl_xor_sync(0xffffffffu, l1, 1);
            l1 += __shfl_xor_sync(0xffffffffu, l1, 2);
            rs0 = rs0 * al0 + l0;
            rs1 = rs1 * al1 + l1;
#pragma unroll
            for (int nt = 0; nt < 8; nt++) {
                o[nt][0] *= al0; o[nt][1] *= al0;
                o[nt][2] *= al1; o[nt][3] *= al1;
            }
            // ---- O += P V : rearrange P C-frag -> A-frag via shuffles ----
#pragma unroll
            for (int kt = 0; kt < 8; kt++) {
                float v00 = __shfl_sync(0xffffffffu, s[kt][0], src0);
                float v01 = __shfl_sync(0xffffffffu, s[kt][1], src0);
                float v02 = __shfl_sync(0xffffffffu, s[kt][2], src0);
                float v03 = __shfl_sync(0xffffffffu, s[kt][3], src0);
                float v10 = __shfl_sync(0xffffffffu, s[kt][0], src1);
                float v11 = __shfl_sync(0xffffffffu, s[kt][1], src1);
                float v12 = __shfl_sync(0xffffffffu, s[kt][2], src1);
                float v13 = __shfl_sync(0xffffffffu, s[kt][3], src1);
                float a[4];
                a[0] = hi ? v01 : v00;   // P[g   ][kt*8+tig]
                a[1] = hi ? v03 : v02;   // P[g+8 ][kt*8+tig]
                a[2] = hi ? v11 : v10;   // P[g   ][kt*8+tig+4]
                a[3] = hi ? v13 : v12;   // P[g+8 ][kt*8+tig+4]
                int kb = kt * 8 + tig;
#pragma unroll
                for (int nt = 0; nt < 8; nt++) {
                    float bfr[2] = { Vs[kb * 72 + nt * 8 + g],
                                     Vs[(kb + 4) * 72 + nt * 8 + g] };
                    mma8(o[nt], a, bfr);
                }
            }
        }
        __syncthreads();
    }

    // ---- epilogue ----
    float inv0 = 1.0f / rs0, inv1 = 1.0f / rs1;
    int r0 = i0 + warp * 16 + g;
#pragma unroll
    for (int nt = 0; nt < 8; nt++) {
        int col = h * HDD + nt * 8 + 2 * tig;
        float* p0 = ao + (size_t)(b * TT + r0) * DD + col;
        float* p1 = ao + (size_t)(b * TT + r0 + 8) * DD + col;
        *(float2*)p0 = make_float2(tf32r(o[nt][0] * inv0), tf32r(o[nt][1] * inv0));
        *(float2*)p1 = make_float2(tf32r(o[nt][2] * inv1), tf32r(o[nt][3] * inv1));
    }
}

// ---------------------------------------------------------------------------
// Launch
// ---------------------------------------------------------------------------
extern "C" void kernel_launch(void* const* d_in, const int* in_sizes, int n_in,
                              void* d_out, int out_size)
{
    const float* x      = (const float*)d_in[0];
    const float* w_pre  = (const float*)d_in[1];
    const float* wq     = (const float*)d_in[2];
    const float* wk     = (const float*)d_in[3];
    const float* wv     = (const float*)d_in[4];
    const float* wo     = (const float*)d_in[5];
    const float* w_attn = (const float*)d_in[6];
    const float* w1     = (const float*)d_in[7];
    const float* w2     = (const float*)d_in[8];
    const float* w_ffn  = (const float*)d_in[9];
    float* out = (float*)d_out;

    float *h_, *q_, *k_, *v_, *ao_, *tmp_, *y_, *mid_, *w_;
    cudaGetSymbolAddress((void**)&h_,   g_h);
    cudaGetSymbolAddress((void**)&q_,   g_q);
    cudaGetSymbolAddress((void**)&k_,   g_k);
    cudaGetSymbolAddress((void**)&v_,   g_v);
    cudaGetSymbolAddress((void**)&ao_,  g_ao);
    cudaGetSymbolAddress((void**)&tmp_, g_tmp);
    cudaGetSymbolAddress((void**)&y_,   g_y);
    cudaGetSymbolAddress((void**)&mid_, g_mid);
    cudaGetSymbolAddress((void**)&w_,   g_w);

    // 0) round weights to tf32
    round4_kernel<<<(DD*DD/4 + 255)/256, 256>>>((const float4*)wq, (float4*)(w_ + WQ_OFF), DD*DD/4);
    round4_kernel<<<(DD*DD/4 + 255)/256, 256>>>((const float4*)wk, (float4*)(w_ + WK_OFF), DD*DD/4);
    round4_kernel<<<(DD*DD/4 + 255)/256, 256>>>((const float4*)wv, (float4*)(w_ + WV_OFF), DD*DD/4);
    round4_kernel<<<(DD*DD/4 + 255)/256, 256>>>((const float4*)wo, (float4*)(w_ + WO_OFF), DD*DD/4);
    round4_kernel<<<(DD*FFD/4 + 255)/256, 256>>>((const float4*)w1, (float4*)(w_ + W1_OFF), DD*FFD/4);
    round4_kernel<<<(DD*FFD/4 + 255)/256, 256>>>((const float4*)w2, (float4*)(w_ + W2_OFF), DD*FFD/4);

    // 1) h = rmsnorm(x)
    rmsnorm_kernel<1><<<MT, 256>>>(x, nullptr, w_pre, h_);

    // 2) q, k, v projections
    {
        dim3 g(DD / 128, MT / 128);
        tgemm_kernel<0, 1><<<g, 256>>>(h_, w_ + WQ_OFF, q_, MT, DD, DD);
        tgemm_kernel<0, 1><<<g, 256>>>(h_, w_ + WK_OFF, k_, MT, DD, DD);
        tgemm_kernel<0, 1><<<g, 256>>>(h_, w_ + WV_OFF, v_, MT, DD, DD);
    }

    // 3) fused flash attention
    {
        dim3 g(TT / 128, BB * HH);
        flash_kernel<<<g, 256>>>(q_, k_, v_, ao_);
    }

    // 4) o-proj + residual norm
    {
        dim3 g(DD / 128, MT / 128);
        tgemm_kernel<0, 0><<<g, 256>>>(ao_, w_ + WO_OFF, tmp_, MT, DD, DD);
    }
    rmsnorm_kernel<1><<<MT, 256>>>(h_, tmp_, w_attn, y_);

    // 5) FFN
    {
        dim3 g(FFD / 128, MT / 128);
        tgemm_kernel<1, 1><<<g, 256>>>(y_, w_ + W1_OFF, mid_, MT, FFD, DD);
    }
    {
        dim3 g(DD / 128, MT / 128);
        tgemm_kernel<0, 0><<<g, 256>>>(mid_, w_ + W2_OFF, tmp_, MT, DD, FFD);
    }
    rmsnorm_kernel<0><<<MT, 256>>>(y_, tmp_, w_ffn, out);
}